// round 5
// baseline (speedup 1.0000x reference)
#include <cuda_runtime.h>
#include <math.h>

// Scratch for per-block partial sums (no device allocation allowed).
#define MAX_BLOCKS 65536
__device__ float g_partials[MAX_BLOCKS];

static constexpr int D = 512;          // feature dim (float32)
static constexpr int BLOCK = 256;      // 8 warps per block, 1 warp per edge

// Kernel 1: one warp per edge. Gather two rows, dot, BCE-with-logits term,
// deterministic block reduce into g_partials[blockIdx.x].
__global__ void __launch_bounds__(BLOCK) edge_loss_kernel(
    const float* __restrict__ feat,
    const int*   __restrict__ pos_src,
    const int*   __restrict__ pos_dst,
    const int*   __restrict__ neg_src,
    const int*   __restrict__ neg_dst,
    int e_pos, int e_total)
{
    const int warp_global = (blockIdx.x * BLOCK + threadIdx.x) >> 5;
    const int lane = threadIdx.x & 31;
    const int wid  = threadIdx.x >> 5;

    float term = 0.0f;

    if (warp_global < e_total) {
        int s, d;
        const bool is_pos = (warp_global < e_pos);
        if (is_pos) {
            s = pos_src[warp_global];
            d = pos_dst[warp_global];
        } else {
            s = neg_src[warp_global - e_pos];
            d = neg_dst[warp_global - e_pos];
        }

        const float4* __restrict__ u =
            reinterpret_cast<const float4*>(feat + (size_t)s * D);
        const float4* __restrict__ v =
            reinterpret_cast<const float4*>(feat + (size_t)d * D);

        // 512 floats = 128 float4 per row; each lane takes 4 at stride 32.
        // Load all 8 vectors up front for maximum MLP.
        float4 a0 = u[lane +  0];
        float4 a1 = u[lane + 32];
        float4 a2 = u[lane + 64];
        float4 a3 = u[lane + 96];
        float4 b0 = v[lane +  0];
        float4 b1 = v[lane + 32];
        float4 b2 = v[lane + 64];
        float4 b3 = v[lane + 96];

        float acc = 0.0f;
        acc = fmaf(a0.x, b0.x, acc); acc = fmaf(a0.y, b0.y, acc);
        acc = fmaf(a0.z, b0.z, acc); acc = fmaf(a0.w, b0.w, acc);
        acc = fmaf(a1.x, b1.x, acc); acc = fmaf(a1.y, b1.y, acc);
        acc = fmaf(a1.z, b1.z, acc); acc = fmaf(a1.w, b1.w, acc);
        acc = fmaf(a2.x, b2.x, acc); acc = fmaf(a2.y, b2.y, acc);
        acc = fmaf(a2.z, b2.z, acc); acc = fmaf(a2.w, b2.w, acc);
        acc = fmaf(a3.x, b3.x, acc); acc = fmaf(a3.y, b3.y, acc);
        acc = fmaf(a3.z, b3.z, acc); acc = fmaf(a3.w, b3.w, acc);

        // Warp reduce (deterministic tree).
        #pragma unroll
        for (int off = 16; off > 0; off >>= 1)
            acc += __shfl_xor_sync(0xffffffffu, acc, off);

        // Numerically stable BCE-with-logits term.
        const float sc  = acc;
        const float lab = is_pos ? 1.0f : 0.0f;
        term = fmaxf(sc, 0.0f) - sc * lab + log1pf(expf(-fabsf(sc)));
    }

    // Block reduce: lane 0 of each warp posts its term; thread 0 sums in
    // a fixed order (deterministic).
    __shared__ float smem[BLOCK / 32];
    if (lane == 0) smem[wid] = term;
    __syncthreads();
    if (threadIdx.x == 0) {
        float sum = 0.0f;
        #pragma unroll
        for (int i = 0; i < BLOCK / 32; i++) sum += smem[i];
        g_partials[blockIdx.x] = sum;
    }
}

// Kernel 2: single-block deterministic reduce of block partials -> mean.
__global__ void __launch_bounds__(1024) final_reduce_kernel(
    int n_partials, float inv_total, float* __restrict__ out)
{
    __shared__ float sm[1024];
    float acc = 0.0f;
    for (int i = threadIdx.x; i < n_partials; i += 1024)
        acc += g_partials[i];
    sm[threadIdx.x] = acc;
    __syncthreads();
    #pragma unroll
    for (int s = 512; s > 0; s >>= 1) {
        if (threadIdx.x < s) sm[threadIdx.x] += sm[threadIdx.x + s];
        __syncthreads();
    }
    if (threadIdx.x == 0) *out = sm[0] * inv_total;
}

extern "C" void kernel_launch(void* const* d_in, const int* in_sizes, int n_in,
                              void* d_out, int out_size)
{
    const float* feat    = (const float*)d_in[0];
    const int*   pos_src = (const int*)d_in[1];
    const int*   pos_dst = (const int*)d_in[2];
    const int*   neg_src = (const int*)d_in[3];
    const int*   neg_dst = (const int*)d_in[4];
    float* out = (float*)d_out;

    const int e_pos   = in_sizes[1];
    const int e_neg   = in_sizes[3];
    const int e_total = e_pos + e_neg;

    const int warps_per_block = BLOCK / 32;
    int n_blocks = (e_total + warps_per_block - 1) / warps_per_block;
    if (n_blocks > MAX_BLOCKS) n_blocks = MAX_BLOCKS;  // e_total=200k -> 25k blocks, fits

    edge_loss_kernel<<<n_blocks, BLOCK>>>(feat, pos_src, pos_dst,
                                          neg_src, neg_dst, e_pos, e_total);
    final_reduce_kernel<<<1, 1024>>>(n_blocks, 1.0f / (float)e_total, out);
}